// round 15
// baseline (speedup 1.0000x reference)
#include <cuda_runtime.h>

// x[64, 64, 64, 128] fp32.
//   out1 = FWHT along axis 1 (i), element stride 8192
//   out2 = FWHT along axis 2 (j) of out1, element stride 128
// d_out = [out1 | out2].
//
// Produce-then-consume lag pipeline with cross-wave lag (round 14, LAG now 24)
// and SINGLE-THREAD cumulative fences:
//   pass-1 end:  __syncthreads(); thread0: __threadfence(); atomicAdd(cnt).
//   pass-2 gate: thread0 spins + __threadfence(); __syncthreads().
// PTX fences are cumulative, so t0's gpu-scope fence after the block barrier
// releases ALL threads' out1 stores; the other 7 warps never stall on store
// drain and fall straight from their last STG into pass-2 loads.
// out1 re-reads are L2 hits (hot footprint ~(LAG+wave)*2MB ~ 76MB < 126MB);
// out1 reaches DRAM only via writeback -> ~384 MB total traffic.
// Counters self-reset (last pass-2 block clears both) -> graph-replay safe,
// one kernel launch.

#define THREADS 256
#define NB 64
#define BPB 32                       // blocks per batch-pass
#define LAG 24
#define GRID ((NB + LAG) * BPB)      // 2816

__device__ int g_cnt1[NB];           // pass-1 completions per batch
__device__ int g_cnt2[NB];           // pass-2 completions per batch

__device__ __forceinline__ void butterfly64(float v[64])
{
#pragma unroll
    for (int h = 1; h < 64; h <<= 1)
#pragma unroll
        for (int s = 0; s < 64; s += 2 * h)
#pragma unroll
            for (int k = 0; k < h; k++) {
                float a = v[s + k], b = v[s + k + h];
                v[s + k]     = a + b;
                v[s + k + h] = a - b;
            }
}

__global__ __launch_bounds__(THREADS)
void wht2_lag(const float* __restrict__ x,
              float* __restrict__ out1,
              float* __restrict__ out2)
{
    const int grp = blockIdx.x / BPB;            // 0 .. NB+LAG-1
    const int sub = blockIdx.x % BPB;
    const unsigned col = (unsigned)sub * THREADS + threadIdx.x;   // 0..8191

    float v[64];

    // ---------------- pass 1: out1[grp] = FWHT_i(x[grp]) ----------------
    if (grp < NB) {
        const size_t bbase = (size_t)grp * (64u * 8192u);
        const float* px = x + bbase + col;           // col = (j,c)
#pragma unroll
        for (int k = 0; k < 64; k++)
            v[k] = __ldcs(px + (size_t)k * 8192);    // use-once read of x

        butterfly64(v);

        float* po = out1 + bbase + col;
#pragma unroll
        for (int k = 0; k < 64; k++)
            po[(size_t)k * 8192] = v[k];             // keep in L2 for pass 2

        // cumulative release: barrier, then t0-only gpu fence + signal.
        __syncthreads();
        if (threadIdx.x == 0) {
            __threadfence();
            atomicAdd(&g_cnt1[grp], 1);
        }
    }

    // ---------------- pass 2: out2[m] = FWHT_j(out1[m]), m = grp-LAG ----------------
    if (grp >= LAG) {
        const int m = grp - LAG;

        // cumulative acquire: t0 spins + fences, then barrier.
        if (threadIdx.x == 0) {
            while (*(volatile int*)&g_cnt1[m] < BPB)  // produced a wave ago -> ~no spin
                __nanosleep(32);
            __threadfence();
        }
        __syncthreads();

        const size_t mbase = (size_t)m * (64u * 8192u);
        const size_t base  = mbase + (size_t)(col >> 7) * 8192u + (col & 127u);
        const float* pi = out1 + base;
#pragma unroll
        for (int k = 0; k < 64; k++)
            v[k] = __ldcs(pi + (size_t)k * 128);      // L2-hot; evict after use

        butterfly64(v);

        float* po = out2 + base;
#pragma unroll
        for (int k = 0; k < 64; k++)
            __stcs(po + (size_t)k * 128, v[k]);       // use-once write

        // self-reset: last finishing pass-2 block clears both counters
        // (all waiters on g_cnt1[m] have already passed the spin).
        __syncthreads();
        if (threadIdx.x == 0) {
            int done = atomicAdd(&g_cnt2[m], 1) + 1;
            if (done == BPB) {
                atomicExch(&g_cnt2[m], 0);
                atomicExch(&g_cnt1[m], 0);
            }
        }
    }
}

extern "C" void kernel_launch(void* const* d_in, const int* in_sizes, int n_in,
                              void* d_out, int out_size)
{
    const float* x = (const float*)d_in[0];
    float* out1 = (float*)d_out;
    float* out2 = out1 + (size_t)64 * 64 * 64 * 128;

    wht2_lag<<<GRID, THREADS>>>(x, out1, out2);
}

// round 16
// speedup vs baseline: 1.2209x; 1.2209x over previous
#include <cuda_runtime.h>

// x[64, 64, 64, 128] fp32.
//   out1 = FWHT along axis 1 (i), element stride 8192
//   out2 = FWHT along axis 2 (j) of out1, element stride 128
// d_out = [out1 | out2].
//
// Round-14 kernel (best: produce-then-consume, cross-wave LAG=16, all-thread
// fences) with ONE change: out2 is written with __stwt (write-through, no L2
// allocation). out2 lines are dead (never re-read); keeping them out of L2
// preserves the hot out1 producer->consumer window and removes the deferred
// dirty-writeback bursts from the DRAM schedule.
// out1 re-reads are L2 hits (hot footprint ~(LAG+wave)*2MB ~ 60MB < 126MB);
// out1 reaches DRAM only via writeback -> ~384 MB total traffic.
// Counters self-reset (last pass-2 block clears both) -> graph-replay safe.

#define THREADS 256
#define NB 64
#define BPB 32                       // blocks per batch-pass
#define LAG 16
#define GRID ((NB + LAG) * BPB)      // 2560

__device__ int g_cnt1[NB];           // pass-1 completions per batch
__device__ int g_cnt2[NB];           // pass-2 completions per batch

__device__ __forceinline__ void butterfly64(float v[64])
{
#pragma unroll
    for (int h = 1; h < 64; h <<= 1)
#pragma unroll
        for (int s = 0; s < 64; s += 2 * h)
#pragma unroll
            for (int k = 0; k < h; k++) {
                float a = v[s + k], b = v[s + k + h];
                v[s + k]     = a + b;
                v[s + k + h] = a - b;
            }
}

__global__ __launch_bounds__(THREADS)
void wht2_lag(const float* __restrict__ x,
              float* __restrict__ out1,
              float* __restrict__ out2)
{
    const int grp = blockIdx.x / BPB;            // 0 .. NB+LAG-1
    const int sub = blockIdx.x % BPB;
    const unsigned col = (unsigned)sub * THREADS + threadIdx.x;   // 0..8191

    float v[64];

    // ---------------- pass 1: out1[grp] = FWHT_i(x[grp]) ----------------
    if (grp < NB) {
        const size_t bbase = (size_t)grp * (64u * 8192u);
        const float* px = x + bbase + col;           // col = (j,c)
#pragma unroll
        for (int k = 0; k < 64; k++)
            v[k] = __ldcs(px + (size_t)k * 8192);    // use-once read of x

        butterfly64(v);

        float* po = out1 + bbase + col;
#pragma unroll
        for (int k = 0; k < 64; k++)
            po[(size_t)k * 8192] = v[k];             // keep in L2 for pass 2

        __threadfence();                              // release out1 stores
        __syncthreads();
        if (threadIdx.x == 0)
            atomicAdd(&g_cnt1[grp], 1);
    }

    // ---------------- pass 2: out2[m] = FWHT_j(out1[m]), m = grp-LAG ----------------
    if (grp >= LAG) {
        const int m = grp - LAG;

        if (threadIdx.x == 0) {
            while (*(volatile int*)&g_cnt1[m] < BPB)   // produced a wave ago -> ~no spin
                __nanosleep(32);
        }
        __syncthreads();
        __threadfence();                               // acquire

        const size_t mbase = (size_t)m * (64u * 8192u);
        const size_t base  = mbase + (size_t)(col >> 7) * 8192u + (col & 127u);
        const float* pi = out1 + base;
#pragma unroll
        for (int k = 0; k < 64; k++)
            v[k] = __ldcs(pi + (size_t)k * 128);      // L2-hot; evict after use

        butterfly64(v);

        float* po = out2 + base;
#pragma unroll
        for (int k = 0; k < 64; k++)
            __stwt(po + (size_t)k * 128, v[k]);       // write-through: no L2 alloc

        // self-reset: last finishing pass-2 block clears both counters
        // (all waiters on g_cnt1[m] have already passed the spin).
        __syncthreads();
        if (threadIdx.x == 0) {
            int done = atomicAdd(&g_cnt2[m], 1) + 1;
            if (done == BPB) {
                atomicExch(&g_cnt2[m], 0);
                atomicExch(&g_cnt1[m], 0);
            }
        }
    }
}

extern "C" void kernel_launch(void* const* d_in, const int* in_sizes, int n_in,
                              void* d_out, int out_size)
{
    const float* x = (const float*)d_in[0];
    float* out1 = (float*)d_out;
    float* out2 = out1 + (size_t)64 * 64 * 64 * 128;

    wht2_lag<<<GRID, THREADS>>>(x, out1, out2);
}

// round 17
// speedup vs baseline: 1.2597x; 1.0318x over previous
#include <cuda_runtime.h>

// x[64, 64, 64, 128] fp32.
//   out1 = FWHT along axis 1 (i), element stride 8192
//   out2 = FWHT along axis 2 (j) of out1, element stride 128
// d_out = [out1 | out2].
//
// Warp-specialized lag pipeline: in every 256-thread block,
//   warps 0-3 (producer half): pass 1 of batch grp   (DRAM reads -> out1)
//   warps 4-7 (consumer half): pass 2 of batch grp-16 (L2 reads -> out2)
// run CONCURRENTLY, so each SM always carries both DRAM-read and DRAM-write
// streams -> no phase alignment, higher DRAM busy%.
// Cross-wave lag: 64 blocks/group, ~444 resident blocks => wave span ~7
// groups; LAG=16 >> 7, so a consumer's dependency was produced a full wave
// earlier (spin ~ 0 even at block start; no intra-wave deadlock pressure).
// out1 re-reads are L2 hits (hot footprint ~(16+7)*2MB ~ 46MB << 126MB);
// out1 reaches DRAM only via writeback -> ~384 MB total traffic.
// Sync: named barrier per half + single-thread cumulative fence/signal.
// Counters self-reset (last consumer block clears both) -> graph-replay safe.

#define THREADS 256
#define HALF 128
#define NB 64
#define BPB 64                       // 128-column units per batch-pass
#define LAG 16
#define GRID ((NB + LAG) * BPB)      // 5120

__device__ int g_cnt1[NB];           // pass-1 completions per batch
__device__ int g_cnt2[NB];           // pass-2 completions per batch

__device__ __forceinline__ void bar_named(int id, int count)
{
    asm volatile("bar.sync %0, %1;" :: "r"(id), "r"(count) : "memory");
}

__device__ __forceinline__ void butterfly64(float v[64])
{
#pragma unroll
    for (int h = 1; h < 64; h <<= 1)
#pragma unroll
        for (int s = 0; s < 64; s += 2 * h)
#pragma unroll
            for (int k = 0; k < h; k++) {
                float a = v[s + k], b = v[s + k + h];
                v[s + k]     = a + b;
                v[s + k + h] = a - b;
            }
}

__global__ __launch_bounds__(THREADS)
void wht2_ws(const float* __restrict__ x,
             float* __restrict__ out1,
             float* __restrict__ out2)
{
    const int grp  = blockIdx.x / BPB;           // 0 .. NB+LAG-1
    const int sub  = blockIdx.x % BPB;
    const int tid  = threadIdx.x;
    const bool producer = (tid < HALF);
    const int  ht  = producer ? tid : (tid - HALF);     // 0..127 within half
    const unsigned col = (unsigned)sub * HALF + ht;     // 0..8191

    float v[64];

    if (producer) {
        // ---------------- pass 1: out1[grp] = FWHT_i(x[grp]) ----------------
        if (grp < NB) {
            const size_t bbase = (size_t)grp * (64u * 8192u);
            const float* px = x + bbase + col;          // col = (j,c)
#pragma unroll
            for (int k = 0; k < 64; k++)
                v[k] = __ldcs(px + (size_t)k * 8192);   // use-once read of x

            butterfly64(v);

            float* po = out1 + bbase + col;
#pragma unroll
            for (int k = 0; k < 64; k++)
                po[(size_t)k * 8192] = v[k];            // keep in L2 for pass 2

            // release: half-barrier, then one thread fences + signals
            bar_named(1, HALF);
            if (ht == 0) {
                __threadfence();
                atomicAdd(&g_cnt1[grp], 1);
            }
        }
    } else {
        // ---------------- pass 2: out2[m] = FWHT_j(out1[m]) ----------------
        if (grp >= LAG) {
            const int m = grp - LAG;

            // acquire: one thread spins + fences, then half-barrier
            if (ht == 0) {
                while (*(volatile int*)&g_cnt1[m] < BPB)  // produced a wave ago
                    __nanosleep(32);
                __threadfence();
            }
            bar_named(2, HALF);

            const size_t mbase = (size_t)m * (64u * 8192u);
            const size_t base  = mbase + (size_t)(col >> 7) * 8192u + (col & 127u);
            const float* pi = out1 + base;
#pragma unroll
            for (int k = 0; k < 64; k++)
                v[k] = __ldcs(pi + (size_t)k * 128);    // L2-hot; evict after use

            butterfly64(v);

            float* po = out2 + base;
#pragma unroll
            for (int k = 0; k < 64; k++)
                __stcs(po + (size_t)k * 128, v[k]);     // use-once write

            // self-reset: last finishing consumer block clears both counters
            bar_named(2, HALF);
            if (ht == 0) {
                int done = atomicAdd(&g_cnt2[m], 1) + 1;
                if (done == BPB) {
                    atomicExch(&g_cnt2[m], 0);
                    atomicExch(&g_cnt1[m], 0);
                }
            }
        }
    }
}

extern "C" void kernel_launch(void* const* d_in, const int* in_sizes, int n_in,
                              void* d_out, int out_size)
{
    const float* x = (const float*)d_in[0];
    float* out1 = (float*)d_out;
    float* out2 = out1 + (size_t)64 * 64 * 64 * 128;

    wht2_ws<<<GRID, THREADS>>>(x, out1, out2);
}